// round 3
// baseline (speedup 1.0000x reference)
#include <cuda_runtime.h>

#define NEG_INF -1.0e9f

// Problem sizes (fixed by the reference)
#define B 8
#define N 512
#define D 256
#define DH 64

#define BM 32            // rows per attention block
#define BN 64            // K/V chunk rows
#define ATTN_BLOCKS (B * (N / BM))      // 128
#define COPY_BLOCKS 444                  // 148 SMs * 3 co-resident copy CTAs
#define E4_COUNT ((size_t)B * N * N * 32 / 4)   // 16,777,216 float4

// smem layout (floats): Qs[32*65] Ks[64*65] Vs[64*65] Ps[32*80]
#define QS_STRIDE 65
#define KS_STRIDE 65
#define PS_STRIDE 80
#define SMEM_FLOATS (BM * QS_STRIDE + BN * KS_STRIDE + BN * KS_STRIDE + BM * PS_STRIDE)

// Scratch for Q, K, V projections (allocation-free: __device__ globals)
__device__ float d_Q[B * N * DH];
__device__ float d_K[B * N * DH];
__device__ float d_V[B * N * DH];

// ---------------------------------------------------------------------------
// QKV projection: one block per (b, n) row.
// ---------------------------------------------------------------------------
__global__ void qkv_kernel(const float* __restrict__ x, const int* __restrict__ mask,
                           const float* __restrict__ Wq, const float* __restrict__ bq,
                           const float* __restrict__ Wk, const float* __restrict__ bk,
                           const float* __restrict__ Wv, const float* __restrict__ bv) {
    int row = blockIdx.x;  // 0..B*N-1
    __shared__ float xs[D];
    int t = threadIdx.x;
    xs[t] = x[row * D + t];
    __syncthreads();
    if (t < 3 * DH) {
        int which = t >> 6;       // 0=Q, 1=K, 2=V
        int col = t & (DH - 1);
        const float* W = (which == 0) ? Wq : (which == 1) ? Wk : Wv;
        const float* Bb = (which == 0) ? bq : (which == 1) ? bk : bv;
        float acc = Bb[col];
#pragma unroll 16
        for (int k = 0; k < D; k++)
            acc = fmaf(xs[k], W[k * DH + col], acc);
        float m = (float)mask[row];
        float* O = (which == 0) ? d_Q : (which == 1) ? d_K : d_V;
        O[row * DH + col] = acc * m;
    }
}

// ---------------------------------------------------------------------------
// Fused: blocks [0,128) = flash-style attention (32 rows each),
//        blocks [128,572) = float4 grid-stride copy of e -> out tail.
// Attention: online softmax, K/V streamed in 64-row chunks, P chunk kept in
// a small padded smem tile (intra-warp producer/consumer -> __syncwarp only).
// ---------------------------------------------------------------------------
__global__ __launch_bounds__(256) void fused_kernel(const int* __restrict__ mask,
                                                    float* __restrict__ out,
                                                    const float4* __restrict__ e4,
                                                    float4* __restrict__ o4) {
    extern __shared__ float sm[];

    if (blockIdx.x >= ATTN_BLOCKS) {
        // ---- copy path: e passthrough ----
        size_t tid = (size_t)(blockIdx.x - ATTN_BLOCKS) * 256 + threadIdx.x;
        const size_t NTH = (size_t)COPY_BLOCKS * 256;
        size_t i = tid;
        for (; i + 3 * NTH < E4_COUNT; i += 4 * NTH) {
            float4 a = e4[i];
            float4 b = e4[i + NTH];
            float4 c = e4[i + 2 * NTH];
            float4 d = e4[i + 3 * NTH];
            o4[i] = a;
            o4[i + NTH] = b;
            o4[i + 2 * NTH] = c;
            o4[i + 3 * NTH] = d;
        }
        for (; i < E4_COUNT; i += NTH) o4[i] = e4[i];
        return;
    }

    // ---- attention path ----
    float* Qs = sm;                                    // 32*65
    float* Ks = sm + BM * QS_STRIDE;                   // 64*65
    float* Vs = Ks + BN * KS_STRIDE;                   // 64*65
    float* Ps = Vs + BN * KS_STRIDE;                   // 32*80
    __shared__ float im[BM], jm[BN];

    int b = blockIdx.x >> 4;
    int i0 = (blockIdx.x & 15) * BM;
    int t = threadIdx.x, tx = t & 15, ty = t >> 4;
    int i_0 = 2 * ty, i_1 = 2 * ty + 1;

    const float* Qb = d_Q + (b * N + i0) * DH;
    const float* Kb = d_K + b * N * DH;
    const float* Vb = d_V + b * N * DH;

    // Load Q tile + row masks
    for (int l = t; l < BM * DH; l += 256) {
        int r = l >> 6, c = l & 63;
        Qs[r * QS_STRIDE + c] = Qb[r * DH + c];
    }
    if (t < BM) im[t] = (float)mask[b * N + i0 + t];
    __syncthreads();

    float m0 = NEG_INF, m1 = NEG_INF;   // running row max
    float l0 = 0.f, l1 = 0.f;           // running exp-sum
    float o0[4] = {0.f, 0.f, 0.f, 0.f};
    float o1[4] = {0.f, 0.f, 0.f, 0.f};
    float mi0 = im[i_0], mi1 = im[i_1];

    for (int jc = 0; jc < N / BN; jc++) {
        int j0 = jc * BN;
        // Load K and V chunks
        for (int l = t; l < BN * DH; l += 256) {
            int r = l >> 6, c = l & 63;
            Ks[r * KS_STRIDE + c] = Kb[(j0 + r) * DH + c];
            Vs[r * KS_STRIDE + c] = Vb[(j0 + r) * DH + c];
        }
        if (t < BN) jm[t] = (float)mask[b * N + j0 + t];
        __syncthreads();

        // scores: s[2][4]
        float a0[4] = {0.f, 0.f, 0.f, 0.f};
        float a1[4] = {0.f, 0.f, 0.f, 0.f};
#pragma unroll 8
        for (int k = 0; k < DH; k++) {
            float q0 = Qs[i_0 * QS_STRIDE + k];
            float q1 = Qs[i_1 * QS_STRIDE + k];
#pragma unroll
            for (int c = 0; c < 4; c++) {
                float kk = Ks[(tx + 16 * c) * KS_STRIDE + k];
                a0[c] = fmaf(q0, kk, a0[c]);
                a1[c] = fmaf(q1, kk, a1[c]);
            }
        }
        // mask + scale
        float s0[4], s1[4];
#pragma unroll
        for (int c = 0; c < 4; c++) {
            float mj = jm[tx + 16 * c];
            s0[c] = (mi0 * mj != 0.f) ? a0[c] * 0.125f : NEG_INF;
            s1[c] = (mi1 * mj != 0.f) ? a1[c] * 0.125f : NEG_INF;
        }
        // chunk max (4 regs + 16-lane shuffle reduce)
        float mc0 = fmaxf(fmaxf(s0[0], s0[1]), fmaxf(s0[2], s0[3]));
        float mc1 = fmaxf(fmaxf(s1[0], s1[1]), fmaxf(s1[2], s1[3]));
#pragma unroll
        for (int d = 8; d; d >>= 1) {
            mc0 = fmaxf(mc0, __shfl_xor_sync(0xffffffffu, mc0, d));
            mc1 = fmaxf(mc1, __shfl_xor_sync(0xffffffffu, mc1, d));
        }
        float mn0 = fmaxf(m0, mc0), mn1 = fmaxf(m1, mc1);
        float al0 = __expf(m0 - mn0), al1 = __expf(m1 - mn1);
        m0 = mn0; m1 = mn1;
        // exponentiate, stash P chunk, accumulate sums
        float ls0 = 0.f, ls1 = 0.f;
#pragma unroll
        for (int c = 0; c < 4; c++) {
            float p0 = __expf(s0[c] - mn0);
            float p1 = __expf(s1[c] - mn1);
            Ps[i_0 * PS_STRIDE + tx + 16 * c] = p0;
            Ps[i_1 * PS_STRIDE + tx + 16 * c] = p1;
            ls0 += p0; ls1 += p1;
        }
#pragma unroll
        for (int d = 8; d; d >>= 1) {
            ls0 += __shfl_xor_sync(0xffffffffu, ls0, d);
            ls1 += __shfl_xor_sync(0xffffffffu, ls1, d);
        }
        l0 = l0 * al0 + ls0;
        l1 = l1 * al1 + ls1;
#pragma unroll
        for (int c = 0; c < 4; c++) { o0[c] *= al0; o1[c] *= al1; }

        __syncwarp();   // P rows for this warp are produced/consumed intra-warp

        // o += P @ V chunk
#pragma unroll 4
        for (int jj = 0; jj < BN; jj++) {
            float p0 = Ps[i_0 * PS_STRIDE + jj];
            float p1 = Ps[i_1 * PS_STRIDE + jj];
#pragma unroll
            for (int c = 0; c < 4; c++) {
                float v = Vs[jj * KS_STRIDE + tx + 16 * c];
                o0[c] = fmaf(p0, v, o0[c]);
                o1[c] = fmaf(p1, v, o1[c]);
            }
        }
        __syncthreads();  // Ks/Vs reused next chunk
    }

    float f0 = mi0 / l0;   // l >= 1 always (masked rows contribute exp(0)=1)
    float f1 = mi1 / l1;
#pragma unroll
    for (int c = 0; c < 4; c++) {
        out[(b * N + i0 + i_0) * DH + tx + 16 * c] = o0[c] * f0;
        out[(b * N + i0 + i_1) * DH + tx + 16 * c] = o1[c] * f1;
    }
}

extern "C" void kernel_launch(void* const* d_in, const int* in_sizes, int n_in,
                              void* d_out, int out_size) {
    const float* x  = (const float*)d_in[0];
    const float* e  = (const float*)d_in[1];
    const int* mask = (const int*)d_in[2];
    const float* Wq = (const float*)d_in[3];
    const float* bq = (const float*)d_in[4];
    const float* Wk = (const float*)d_in[5];
    const float* bk = (const float*)d_in[6];
    const float* Wv = (const float*)d_in[7];
    const float* bv = (const float*)d_in[8];
    float* out = (float*)d_out;

    (void)in_sizes; (void)n_in; (void)out_size;

    const size_t OUT_ELEMS = (size_t)B * N * DH;   // 262144

    static bool attr_set = false;
    if (!attr_set) {
        cudaFuncSetAttribute(fused_kernel, cudaFuncAttributeMaxDynamicSharedMemorySize,
                             SMEM_FLOATS * (int)sizeof(float));
        attr_set = true;
    }

    qkv_kernel<<<B * N, 256>>>(x, mask, Wq, bq, Wk, bk, Wv, bv);
    fused_kernel<<<ATTN_BLOCKS + COPY_BLOCKS, 256, SMEM_FLOATS * sizeof(float)>>>(
        mask, out, (const float4*)e, (float4*)(out + OUT_ELEMS));
}

// round 4
// speedup vs baseline: 1.0749x; 1.0749x over previous
#include <cuda_runtime.h>

#define NEG_INF -1.0e9f

// Problem sizes (fixed by the reference)
#define B 8
#define N 512
#define D 256
#define DH 64

#define BM 32            // rows per attention block
#define BN 64            // K/V chunk rows
#define ATTN_BLOCKS (B * (N / BM))               // 128
#define E4_COUNT ((size_t)B * N * N * 32 / 4)    // 16,777,216 float4

// smem layout (floats): Qs[32*65] Ks[64*65] Vs[64*65] Ps[32*80]
#define QS_STRIDE 65
#define KS_STRIDE 65
#define PS_STRIDE 80
#define SMEM_FLOATS (BM * QS_STRIDE + BN * KS_STRIDE + BN * KS_STRIDE + BM * PS_STRIDE)

// Scratch for Q, K, V projections (allocation-free: __device__ globals)
__device__ float d_Q[B * N * DH];
__device__ float d_K[B * N * DH];
__device__ float d_V[B * N * DH];

// ---------------------------------------------------------------------------
// e passthrough: dedicated zero-smem copy kernel (runs on side stream).
// 4 independent float4 loads/stores per iteration for deep MLP.
// ---------------------------------------------------------------------------
#define COPY_BLOCKS 2048
__global__ __launch_bounds__(256) void copy_kernel(const float4* __restrict__ e4,
                                                   float4* __restrict__ o4) {
    const size_t NTH = (size_t)COPY_BLOCKS * 256;
    size_t i = (size_t)blockIdx.x * 256 + threadIdx.x;
    for (; i + 3 * NTH < E4_COUNT; i += 4 * NTH) {
        float4 a = e4[i];
        float4 b = e4[i + NTH];
        float4 c = e4[i + 2 * NTH];
        float4 d = e4[i + 3 * NTH];
        o4[i] = a;
        o4[i + NTH] = b;
        o4[i + 2 * NTH] = c;
        o4[i + 3 * NTH] = d;
    }
    for (; i < E4_COUNT; i += NTH) o4[i] = e4[i];
}

// ---------------------------------------------------------------------------
// QKV projection: one block per (b, n) row.
// ---------------------------------------------------------------------------
__global__ void qkv_kernel(const float* __restrict__ x, const int* __restrict__ mask,
                           const float* __restrict__ Wq, const float* __restrict__ bq,
                           const float* __restrict__ Wk, const float* __restrict__ bk,
                           const float* __restrict__ Wv, const float* __restrict__ bv) {
    int row = blockIdx.x;  // 0..B*N-1
    __shared__ float xs[D];
    int t = threadIdx.x;
    xs[t] = x[row * D + t];
    __syncthreads();
    if (t < 3 * DH) {
        int which = t >> 6;       // 0=Q, 1=K, 2=V
        int col = t & (DH - 1);
        const float* W = (which == 0) ? Wq : (which == 1) ? Wk : Wv;
        const float* Bb = (which == 0) ? bq : (which == 1) ? bk : bv;
        float acc = Bb[col];
#pragma unroll 16
        for (int k = 0; k < D; k++)
            acc = fmaf(xs[k], W[k * DH + col], acc);
        float m = (float)mask[row];
        float* O = (which == 0) ? d_Q : (which == 1) ? d_K : d_V;
        O[row * DH + col] = acc * m;
    }
}

// ---------------------------------------------------------------------------
// Flash-style attention: one block per (b, 32-row i-tile). Online softmax,
// K/V streamed in 64-row chunks, P chunk exchanged through a small padded
// smem tile (intra-warp producer/consumer -> __syncwarp only).
// ---------------------------------------------------------------------------
__global__ __launch_bounds__(256) void attn_kernel(const int* __restrict__ mask,
                                                   float* __restrict__ out) {
    extern __shared__ float sm[];
    float* Qs = sm;                                    // 32*65
    float* Ks = sm + BM * QS_STRIDE;                   // 64*65
    float* Vs = Ks + BN * KS_STRIDE;                   // 64*65
    float* Ps = Vs + BN * KS_STRIDE;                   // 32*80
    __shared__ float im[BM], jm[BN];

    int b = blockIdx.x >> 4;
    int i0 = (blockIdx.x & 15) * BM;
    int t = threadIdx.x, tx = t & 15, ty = t >> 4;
    int i_0 = 2 * ty, i_1 = 2 * ty + 1;

    const float* Qb = d_Q + (b * N + i0) * DH;
    const float* Kb = d_K + b * N * DH;
    const float* Vb = d_V + b * N * DH;

    for (int l = t; l < BM * DH; l += 256) {
        int r = l >> 6, c = l & 63;
        Qs[r * QS_STRIDE + c] = Qb[r * DH + c];
    }
    if (t < BM) im[t] = (float)mask[b * N + i0 + t];
    __syncthreads();

    float m0 = NEG_INF, m1 = NEG_INF;
    float l0 = 0.f, l1 = 0.f;
    float o0[4] = {0.f, 0.f, 0.f, 0.f};
    float o1[4] = {0.f, 0.f, 0.f, 0.f};
    float mi0 = im[i_0], mi1 = im[i_1];

    for (int jc = 0; jc < N / BN; jc++) {
        int j0 = jc * BN;
        for (int l = t; l < BN * DH; l += 256) {
            int r = l >> 6, c = l & 63;
            Ks[r * KS_STRIDE + c] = Kb[(j0 + r) * DH + c];
            Vs[r * KS_STRIDE + c] = Vb[(j0 + r) * DH + c];
        }
        if (t < BN) jm[t] = (float)mask[b * N + j0 + t];
        __syncthreads();

        float a0[4] = {0.f, 0.f, 0.f, 0.f};
        float a1[4] = {0.f, 0.f, 0.f, 0.f};
#pragma unroll 8
        for (int k = 0; k < DH; k++) {
            float q0 = Qs[i_0 * QS_STRIDE + k];
            float q1 = Qs[i_1 * QS_STRIDE + k];
#pragma unroll
            for (int c = 0; c < 4; c++) {
                float kk = Ks[(tx + 16 * c) * KS_STRIDE + k];
                a0[c] = fmaf(q0, kk, a0[c]);
                a1[c] = fmaf(q1, kk, a1[c]);
            }
        }
        float s0[4], s1[4];
#pragma unroll
        for (int c = 0; c < 4; c++) {
            float mj = jm[tx + 16 * c];
            s0[c] = (mi0 * mj != 0.f) ? a0[c] * 0.125f : NEG_INF;
            s1[c] = (mi1 * mj != 0.f) ? a1[c] * 0.125f : NEG_INF;
        }
        float mc0 = fmaxf(fmaxf(s0[0], s0[1]), fmaxf(s0[2], s0[3]));
        float mc1 = fmaxf(fmaxf(s1[0], s1[1]), fmaxf(s1[2], s1[3]));
#pragma unroll
        for (int d = 8; d; d >>= 1) {
            mc0 = fmaxf(mc0, __shfl_xor_sync(0xffffffffu, mc0, d));
            mc1 = fmaxf(mc1, __shfl_xor_sync(0xffffffffu, mc1, d));
        }
        float mn0 = fmaxf(m0, mc0), mn1 = fmaxf(m1, mc1);
        float al0 = __expf(m0 - mn0), al1 = __expf(m1 - mn1);
        m0 = mn0; m1 = mn1;
        float ls0 = 0.f, ls1 = 0.f;
#pragma unroll
        for (int c = 0; c < 4; c++) {
            float p0 = __expf(s0[c] - mn0);
            float p1 = __expf(s1[c] - mn1);
            Ps[i_0 * PS_STRIDE + tx + 16 * c] = p0;
            Ps[i_1 * PS_STRIDE + tx + 16 * c] = p1;
            ls0 += p0; ls1 += p1;
        }
#pragma unroll
        for (int d = 8; d; d >>= 1) {
            ls0 += __shfl_xor_sync(0xffffffffu, ls0, d);
            ls1 += __shfl_xor_sync(0xffffffffu, ls1, d);
        }
        l0 = l0 * al0 + ls0;
        l1 = l1 * al1 + ls1;
#pragma unroll
        for (int c = 0; c < 4; c++) { o0[c] *= al0; o1[c] *= al1; }

        __syncwarp();   // P rows produced/consumed intra-warp

#pragma unroll 4
        for (int jj = 0; jj < BN; jj++) {
            float p0 = Ps[i_0 * PS_STRIDE + jj];
            float p1 = Ps[i_1 * PS_STRIDE + jj];
#pragma unroll
            for (int c = 0; c < 4; c++) {
                float v = Vs[jj * KS_STRIDE + tx + 16 * c];
                o0[c] = fmaf(p0, v, o0[c]);
                o1[c] = fmaf(p1, v, o1[c]);
            }
        }
        __syncthreads();
    }

    float f0 = mi0 / l0;
    float f1 = mi1 / l1;
#pragma unroll
    for (int c = 0; c < 4; c++) {
        out[(b * N + i0 + i_0) * DH + tx + 16 * c] = o0[c] * f0;
        out[(b * N + i0 + i_1) * DH + tx + 16 * c] = o1[c] * f1;
    }
}

// ---------------------------------------------------------------------------
// Launch: fork-join two-stream graph. Copy runs on a side stream (no smem,
// full occupancy) concurrently with qkv -> attn on the main stream.
// ---------------------------------------------------------------------------
static cudaStream_t s_copy = nullptr;
static cudaEvent_t ev_fork = nullptr, ev_join = nullptr;

extern "C" void kernel_launch(void* const* d_in, const int* in_sizes, int n_in,
                              void* d_out, int out_size) {
    const float* x  = (const float*)d_in[0];
    const float* e  = (const float*)d_in[1];
    const int* mask = (const int*)d_in[2];
    const float* Wq = (const float*)d_in[3];
    const float* bq = (const float*)d_in[4];
    const float* Wk = (const float*)d_in[5];
    const float* bk = (const float*)d_in[6];
    const float* Wv = (const float*)d_in[7];
    const float* bv = (const float*)d_in[8];
    float* out = (float*)d_out;

    (void)in_sizes; (void)n_in; (void)out_size;

    const size_t OUT_ELEMS = (size_t)B * N * DH;   // 262144

    if (!s_copy) {
        cudaStreamCreateWithFlags(&s_copy, cudaStreamNonBlocking);
        cudaEventCreateWithFlags(&ev_fork, cudaEventDisableTiming);
        cudaEventCreateWithFlags(&ev_join, cudaEventDisableTiming);
        cudaFuncSetAttribute(attn_kernel, cudaFuncAttributeMaxDynamicSharedMemorySize,
                             SMEM_FLOATS * (int)sizeof(float));
    }

    // Fork: copy e on side stream
    cudaEventRecord(ev_fork, 0);
    cudaStreamWaitEvent(s_copy, ev_fork, 0);
    copy_kernel<<<COPY_BLOCKS, 256, 0, s_copy>>>((const float4*)e,
                                                 (float4*)(out + OUT_ELEMS));
    cudaEventRecord(ev_join, s_copy);

    // Main stream: qkv -> attn
    qkv_kernel<<<B * N, 256>>>(x, mask, Wq, bq, Wk, bk, Wv, bv);
    attn_kernel<<<ATTN_BLOCKS, 256, SMEM_FLOATS * sizeof(float)>>>(mask, out);

    // Join
    cudaStreamWaitEvent(0, ev_join, 0);
}

// round 5
// speedup vs baseline: 1.0890x; 1.0132x over previous
#include <cuda_runtime.h>

#define NEG_INF -1.0e9f

// Problem sizes (fixed by the reference)
#define B 8
#define N 512
#define D 256
#define DH 64

#define BM 16            // rows per attention block
#define BN 64            // K/V chunk rows
#define NC (N / BN)      // 8 chunks
#define ATTN_BLOCKS (B * (N / BM))               // 256
#define E4_COUNT ((size_t)B * N * N * 32 / 4)    // 16,777,216 float4

// float strides (float4-aligned, conflict-free per LDS.128 phase)
#define KSTR 68
#define PSTR 68
#define QSTR 68

// dyn smem floats: Qs[16*68] + K[2][64*68] + V[2][64*68] + Ps[16*68]
#define SMEM_FLOATS (BM * QSTR + 2 * BN * KSTR + 2 * BN * KSTR + BM * PSTR)

// Scratch for Q, K, V projections (allocation-free: __device__ globals)
__device__ float d_Q[B * N * DH];
__device__ float d_K[B * N * DH];
__device__ float d_V[B * N * DH];

__device__ __forceinline__ void cp16(float* s, const float* g) {
    unsigned sa = (unsigned)__cvta_generic_to_shared(s);
    asm volatile("cp.async.cg.shared.global [%0], [%1], 16;" :: "r"(sa), "l"(g));
}
__device__ __forceinline__ void cp_commit() {
    asm volatile("cp.async.commit_group;");
}
template <int NWAIT>
__device__ __forceinline__ void cp_wait() {
    asm volatile("cp.async.wait_group %0;" :: "n"(NWAIT));
}

// ---------------------------------------------------------------------------
// e passthrough: dedicated zero-smem copy kernel (side stream).
// ---------------------------------------------------------------------------
#define COPY_BLOCKS 2048
__global__ __launch_bounds__(256) void copy_kernel(const float4* __restrict__ e4,
                                                   float4* __restrict__ o4) {
    const size_t NTH = (size_t)COPY_BLOCKS * 256;
    size_t i = (size_t)blockIdx.x * 256 + threadIdx.x;
    for (; i + 3 * NTH < E4_COUNT; i += 4 * NTH) {
        float4 a = e4[i];
        float4 b = e4[i + NTH];
        float4 c = e4[i + 2 * NTH];
        float4 d = e4[i + 3 * NTH];
        o4[i] = a;
        o4[i + NTH] = b;
        o4[i + 2 * NTH] = c;
        o4[i + 3 * NTH] = d;
    }
    for (; i < E4_COUNT; i += NTH) o4[i] = e4[i];
}

// ---------------------------------------------------------------------------
// QKV projection: one block per (b, n) row.
// ---------------------------------------------------------------------------
__global__ void qkv_kernel(const float* __restrict__ x, const int* __restrict__ mask,
                           const float* __restrict__ Wq, const float* __restrict__ bq,
                           const float* __restrict__ Wk, const float* __restrict__ bk,
                           const float* __restrict__ Wv, const float* __restrict__ bv) {
    int row = blockIdx.x;  // 0..B*N-1
    __shared__ float xs[D];
    int t = threadIdx.x;
    xs[t] = x[row * D + t];
    __syncthreads();
    if (t < 3 * DH) {
        int which = t >> 6;       // 0=Q, 1=K, 2=V
        int col = t & (DH - 1);
        const float* W = (which == 0) ? Wq : (which == 1) ? Wk : Wv;
        const float* Bb = (which == 0) ? bq : (which == 1) ? bk : bv;
        float acc = Bb[col];
#pragma unroll 16
        for (int k = 0; k < D; k++)
            acc = fmaf(xs[k], W[k * DH + col], acc);
        float m = (float)mask[row];
        float* O = (which == 0) ? d_Q : (which == 1) ? d_K : d_V;
        O[row * DH + col] = acc * m;
    }
}

// ---------------------------------------------------------------------------
// Flash attention, 16 rows per block, cp.async double-buffered K/V.
// Thread (tx = t&15, ty = t>>4): row i = ty.
//   score cols: j = tx + 16c (c<4)   -> P goes through smem
//   output cols: u + 4*tx (float4)   -> V reads + final store vectorized
// ---------------------------------------------------------------------------
__global__ __launch_bounds__(256) void attn_kernel(const int* __restrict__ mask,
                                                   float* __restrict__ out) {
    extern __shared__ float sm[];
    float* Qs = sm;                         // 16*68
    float* Kb0 = Qs + BM * QSTR;            // 2 x 64*68
    float* Vb0 = Kb0 + 2 * BN * KSTR;       // 2 x 64*68
    float* Ps = Vb0 + 2 * BN * KSTR;        // 16*68
    __shared__ float jms[N];

    int b = blockIdx.x >> 5;                // 32 i-tiles per batch
    int i0 = (blockIdx.x & 31) * BM;
    int t = threadIdx.x, tx = t & 15, ty = t >> 4;

    const float* Qg = d_Q + (b * N + i0) * DH;
    const float* Kg = d_K + b * N * DH;
    const float* Vg = d_V + b * N * DH;

    // one-time loads: Q tile, all j masks
    for (int l = t; l < BM * DH; l += 256) {
        int r = l >> 6, c = l & 63;
        Qs[r * QSTR + c] = Qg[r * DH + c];
    }
    jms[t] = (float)mask[b * N + t];
    jms[t + 256] = (float)mask[b * N + t + 256];

    // preload chunk 0 (K and V)
    {
        int idx = t;                        // 1024 float4 per tile, 4 per thread
#pragma unroll
        for (int r = 0; r < 4; r++, idx += 256) {
            int row = idx >> 4, c4 = (idx & 15) << 2;
            cp16(Kb0 + row * KSTR + c4, Kg + row * DH + c4);
            cp16(Vb0 + row * KSTR + c4, Vg + row * DH + c4);
        }
        cp_commit();
    }
    __syncthreads();   // Qs + jms visible

    float mi = jms[i0 + ty - 0];            // row mask (i0+ty within this b)
    mi = (float)((const int*)0 == 0 ? mi : mi); // keep as-is
    mi = jms[i0 + ty];
    float m_run = NEG_INF, l_run = 0.f;
    float o[4] = {0.f, 0.f, 0.f, 0.f};

    for (int jc = 0; jc < NC; jc++) {
        int buf = jc & 1;
        // issue next chunk's loads into other buffer
        if (jc + 1 < NC) {
            int nb = buf ^ 1;
            const float* Kn = Kg + (jc + 1) * BN * DH;
            const float* Vn = Vg + (jc + 1) * BN * DH;
            int idx = t;
#pragma unroll
            for (int r = 0; r < 4; r++, idx += 256) {
                int row = idx >> 4, c4 = (idx & 15) << 2;
                cp16(Kb0 + nb * BN * KSTR + row * KSTR + c4, Kn + row * DH + c4);
                cp16(Vb0 + nb * BN * KSTR + row * KSTR + c4, Vn + row * DH + c4);
            }
            cp_commit();
            cp_wait<1>();
        } else {
            cp_wait<0>();
        }
        __syncthreads();   // chunk jc data visible to all

        const float* Kc = Kb0 + buf * BN * KSTR;
        const float* Vc = Vb0 + buf * BN * KSTR;
        int j0 = jc * BN;

        // ---- scores: rows ty, cols tx+16c ----
        float a[4] = {0.f, 0.f, 0.f, 0.f};
#pragma unroll
        for (int k4 = 0; k4 < 16; k4++) {
            float4 q = *(const float4*)(Qs + ty * QSTR + 4 * k4);
#pragma unroll
            for (int c = 0; c < 4; c++) {
                float4 kk = *(const float4*)(Kc + (tx + 16 * c) * KSTR + 4 * k4);
                a[c] = fmaf(q.x, kk.x, a[c]);
                a[c] = fmaf(q.y, kk.y, a[c]);
                a[c] = fmaf(q.z, kk.z, a[c]);
                a[c] = fmaf(q.w, kk.w, a[c]);
            }
        }
        float s[4];
#pragma unroll
        for (int c = 0; c < 4; c++) {
            float mj = jms[j0 + tx + 16 * c];
            s[c] = (mi * mj != 0.f) ? a[c] * 0.125f : NEG_INF;
        }
        // chunk max over the 16 lanes that share this row
        float mc = fmaxf(fmaxf(s[0], s[1]), fmaxf(s[2], s[3]));
#pragma unroll
        for (int d = 8; d; d >>= 1)
            mc = fmaxf(mc, __shfl_xor_sync(0xffffffffu, mc, d));
        float mn = fmaxf(m_run, mc);
        float al = __expf(m_run - mn);
        m_run = mn;
        float ls = 0.f;
#pragma unroll
        for (int c = 0; c < 4; c++) {
            float p = __expf(s[c] - mn);
            Ps[ty * PSTR + tx + 16 * c] = p;
            ls += p;
        }
#pragma unroll
        for (int d = 8; d; d >>= 1)
            ls += __shfl_xor_sync(0xffffffffu, ls, d);
        l_run = l_run * al + ls;
#pragma unroll
        for (int u = 0; u < 4; u++) o[u] *= al;

        __syncwarp();   // P rows 2w,2w+1 produced & consumed by warp w

        // ---- o += P @ V: output cols 4tx+u ----
#pragma unroll 4
        for (int jj4 = 0; jj4 < 16; jj4++) {
            float4 p4 = *(const float4*)(Ps + ty * PSTR + 4 * jj4);
            const float* Vrow = Vc + (4 * jj4) * KSTR + 4 * tx;
            float4 v0 = *(const float4*)(Vrow);
            float4 v1 = *(const float4*)(Vrow + KSTR);
            float4 v2 = *(const float4*)(Vrow + 2 * KSTR);
            float4 v3 = *(const float4*)(Vrow + 3 * KSTR);
            o[0] = fmaf(p4.x, v0.x, o[0]); o[1] = fmaf(p4.x, v0.y, o[1]);
            o[2] = fmaf(p4.x, v0.z, o[2]); o[3] = fmaf(p4.x, v0.w, o[3]);
            o[0] = fmaf(p4.y, v1.x, o[0]); o[1] = fmaf(p4.y, v1.y, o[1]);
            o[2] = fmaf(p4.y, v1.z, o[2]); o[3] = fmaf(p4.y, v1.w, o[3]);
            o[0] = fmaf(p4.z, v2.x, o[0]); o[1] = fmaf(p4.z, v2.y, o[1]);
            o[2] = fmaf(p4.z, v2.z, o[2]); o[3] = fmaf(p4.z, v2.w, o[3]);
            o[0] = fmaf(p4.w, v3.x, o[0]); o[1] = fmaf(p4.w, v3.y, o[1]);
            o[2] = fmaf(p4.w, v3.z, o[2]); o[3] = fmaf(p4.w, v3.w, o[3]);
        }
        __syncthreads();   // all reads of buf done before it is overwritten
    }

    float f = mi / l_run;   // l_run >= 1 always
    float4 r;
    r.x = o[0] * f; r.y = o[1] * f; r.z = o[2] * f; r.w = o[3] * f;
    *(float4*)(out + (b * N + i0 + ty) * DH + 4 * tx) = r;
}

// ---------------------------------------------------------------------------
// Launch: fork-join two-stream graph.
// ---------------------------------------------------------------------------
static cudaStream_t s_copy = nullptr;
static cudaEvent_t ev_fork = nullptr, ev_join = nullptr;

extern "C" void kernel_launch(void* const* d_in, const int* in_sizes, int n_in,
                              void* d_out, int out_size) {
    const float* x  = (const float*)d_in[0];
    const float* e  = (const float*)d_in[1];
    const int* mask = (const int*)d_in[2];
    const float* Wq = (const float*)d_in[3];
    const float* bq = (const float*)d_in[4];
    const float* Wk = (const float*)d_in[5];
    const float* bk = (const float*)d_in[6];
    const float* Wv = (const float*)d_in[7];
    const float* bv = (const float*)d_in[8];
    float* out = (float*)d_out;

    (void)in_sizes; (void)n_in; (void)out_size;

    const size_t OUT_ELEMS = (size_t)B * N * DH;   // 262144

    if (!s_copy) {
        cudaStreamCreateWithFlags(&s_copy, cudaStreamNonBlocking);
        cudaEventCreateWithFlags(&ev_fork, cudaEventDisableTiming);
        cudaEventCreateWithFlags(&ev_join, cudaEventDisableTiming);
        cudaFuncSetAttribute(attn_kernel, cudaFuncAttributeMaxDynamicSharedMemorySize,
                             SMEM_FLOATS * (int)sizeof(float));
    }

    // Fork: copy e on side stream
    cudaEventRecord(ev_fork, 0);
    cudaStreamWaitEvent(s_copy, ev_fork, 0);
    copy_kernel<<<COPY_BLOCKS, 256, 0, s_copy>>>((const float4*)e,
                                                 (float4*)(out + OUT_ELEMS));
    cudaEventRecord(ev_join, s_copy);

    // Main stream: qkv -> attn
    qkv_kernel<<<B * N, 256>>>(x, mask, Wq, bq, Wk, bk, Wv, bv);
    attn_kernel<<<ATTN_BLOCKS, 256, SMEM_FLOATS * sizeof(float)>>>(mask, out);

    // Join
    cudaStreamWaitEvent(0, ev_join, 0);
}

// round 6
// speedup vs baseline: 1.2705x; 1.1666x over previous
#include <cuda_runtime.h>

#define NEG_INF -1.0e9f

// Problem sizes (fixed by the reference)
#define B 8
#define N 512
#define D 256
#define DH 64

#define BM 32            // rows per attention block
#define BN 16            // K/V chunk rows
#define NC (N / BN)      // 32 chunks
#define ATTN_BLOCKS (B * (N / BM))               // 128
#define GRID_BLOCKS 888                           // attn + copy CTAs, single wave-ish
#define E4_COUNT ((size_t)B * N * N * 32 / 4)    // 16,777,216 float4

// copy tickets
#define CHUNK4 4096                               // float4 per ticket (64 KB)
#define NTICKETS (int)(E4_COUNT / CHUNK4)         // 4096

// smem strides (floats)
#define QSTR 68
#define KSTR 68
#define PSTR 20
// dyn smem floats: Qs[32*68] + K[2][16*68] + V[2][16*68] + Ps[32*20] = 7168 (28 KB)
#define SMEM_FLOATS (BM * QSTR + 2 * BN * KSTR + 2 * BN * KSTR + BM * PSTR)

// Scratch (allocation-free: __device__ globals)
__device__ float d_Q[B * N * DH];
__device__ float d_K[B * N * DH];
__device__ float d_V[B * N * DH];
__device__ int g_ticket;

__device__ __forceinline__ void cp16(float* s, const float* g) {
    unsigned sa = (unsigned)__cvta_generic_to_shared(s);
    asm volatile("cp.async.cg.shared.global [%0], [%1], 16;" :: "r"(sa), "l"(g));
}
__device__ __forceinline__ void cp_commit() {
    asm volatile("cp.async.commit_group;");
}
template <int NWAIT>
__device__ __forceinline__ void cp_wait() {
    asm volatile("cp.async.wait_group %0;" :: "n"(NWAIT));
}

// ---------------------------------------------------------------------------
// QKV projection: one block per (b, n) row.
// ---------------------------------------------------------------------------
__global__ void qkv_kernel(const float* __restrict__ x, const int* __restrict__ mask,
                           const float* __restrict__ Wq, const float* __restrict__ bq,
                           const float* __restrict__ Wk, const float* __restrict__ bk,
                           const float* __restrict__ Wv, const float* __restrict__ bv) {
    int row = blockIdx.x;  // 0..B*N-1
    __shared__ float xs[D];
    int t = threadIdx.x;
    xs[t] = x[row * D + t];
    __syncthreads();
    if (t < 3 * DH) {
        int which = t >> 6;       // 0=Q, 1=K, 2=V
        int col = t & (DH - 1);
        const float* W = (which == 0) ? Wq : (which == 1) ? Wk : Wv;
        const float* Bb = (which == 0) ? bq : (which == 1) ? bk : bv;
        float acc = Bb[col];
#pragma unroll 16
        for (int k = 0; k < D; k++)
            acc = fmaf(xs[k], W[k * DH + col], acc);
        float m = (float)mask[row];
        float* O = (which == 0) ? d_Q : (which == 1) ? d_K : d_V;
        O[row * DH + col] = acc * m;
    }
}

// ---------------------------------------------------------------------------
// Fused kernel: blocks < ATTN_BLOCKS do flash attention on a 32-row i-tile,
// then fall through to the ticket-based copy loop. Other blocks copy only.
// Copy is perfectly balanced by an atomic ticket counter (reset per launch).
// ---------------------------------------------------------------------------
__global__ __launch_bounds__(256) void fused_kernel(const int* __restrict__ mask,
                                                    float* __restrict__ out,
                                                    const float4* __restrict__ e4,
                                                    float4* __restrict__ o4) {
    extern __shared__ float sm[];
    __shared__ float jms[N];
    __shared__ int s_tk;
    int t = threadIdx.x;

    if (blockIdx.x < ATTN_BLOCKS) {
        float* Qs = sm;                      // 32*68
        float* Kb0 = Qs + BM * QSTR;         // 2 x 16*68
        float* Vb0 = Kb0 + 2 * BN * KSTR;    // 2 x 16*68
        float* Ps = Vb0 + 2 * BN * KSTR;     // 32*20

        int b = blockIdx.x >> 4;             // 16 i-tiles per batch
        int i0 = (blockIdx.x & 15) * BM;
        int tx = t & 15, ty = t >> 4;
        int i_0 = 2 * ty, i_1 = 2 * ty + 1;

        const float* Qg = d_Q + (b * N + i0) * DH;
        const float* Kg = d_K + b * N * DH;
        const float* Vg = d_V + b * N * DH;

        // one-time: Q tile + all j masks
        for (int l = t; l < BM * DH; l += 256) {
            int r = l >> 6, c = l & 63;
            Qs[r * QSTR + c] = Qg[r * DH + c];
        }
        jms[t] = (float)mask[b * N + t];
        jms[t + 256] = (float)mask[b * N + t + 256];

        // preload chunk 0 (K and V): 16 rows x 64 floats = 256 float4 each
        {
            int row = t >> 4, c4 = (t & 15) << 2;
            cp16(Kb0 + row * KSTR + c4, Kg + row * DH + c4);
            cp16(Vb0 + row * KSTR + c4, Vg + row * DH + c4);
            cp_commit();
        }
        __syncthreads();

        float mi0 = jms[i0 + i_0], mi1 = jms[i0 + i_1];
        float m0 = NEG_INF, m1 = NEG_INF;
        float l0 = 0.f, l1 = 0.f;
        float o0[4] = {0.f, 0.f, 0.f, 0.f};
        float o1[4] = {0.f, 0.f, 0.f, 0.f};

        for (int jc = 0; jc < NC; jc++) {
            int buf = jc & 1;
            if (jc + 1 < NC) {
                int nb = buf ^ 1;
                const float* Kn = Kg + (jc + 1) * BN * DH;
                const float* Vn = Vg + (jc + 1) * BN * DH;
                int row = t >> 4, c4 = (t & 15) << 2;
                cp16(Kb0 + nb * BN * KSTR + row * KSTR + c4, Kn + row * DH + c4);
                cp16(Vb0 + nb * BN * KSTR + row * KSTR + c4, Vn + row * DH + c4);
                cp_commit();
                cp_wait<1>();
            } else {
                cp_wait<0>();
            }
            __syncthreads();

            const float* Kc = Kb0 + buf * BN * KSTR;
            const float* Vc = Vb0 + buf * BN * KSTR;
            int j0 = jc * BN;

            // ---- scores: rows i_0,i_1; col j = tx ----
            float a0 = 0.f, a1 = 0.f;
#pragma unroll
            for (int k4 = 0; k4 < 16; k4++) {
                float4 q0 = *(const float4*)(Qs + i_0 * QSTR + 4 * k4);
                float4 q1 = *(const float4*)(Qs + i_1 * QSTR + 4 * k4);
                float4 kk = *(const float4*)(Kc + tx * KSTR + 4 * k4);
                a0 = fmaf(q0.x, kk.x, a0); a0 = fmaf(q0.y, kk.y, a0);
                a0 = fmaf(q0.z, kk.z, a0); a0 = fmaf(q0.w, kk.w, a0);
                a1 = fmaf(q1.x, kk.x, a1); a1 = fmaf(q1.y, kk.y, a1);
                a1 = fmaf(q1.z, kk.z, a1); a1 = fmaf(q1.w, kk.w, a1);
            }
            float mj = jms[j0 + tx];
            float s0 = (mi0 * mj != 0.f) ? a0 * 0.125f : NEG_INF;
            float s1 = (mi1 * mj != 0.f) ? a1 * 0.125f : NEG_INF;

            // chunk max over 16 lanes sharing each row
            float mc0 = s0, mc1 = s1;
#pragma unroll
            for (int d = 8; d; d >>= 1) {
                mc0 = fmaxf(mc0, __shfl_xor_sync(0xffffffffu, mc0, d));
                mc1 = fmaxf(mc1, __shfl_xor_sync(0xffffffffu, mc1, d));
            }
            float mn0 = fmaxf(m0, mc0), mn1 = fmaxf(m1, mc1);
            float al0 = __expf(m0 - mn0), al1 = __expf(m1 - mn1);
            m0 = mn0; m1 = mn1;
            float p0 = __expf(s0 - mn0);
            float p1 = __expf(s1 - mn1);
            Ps[i_0 * PSTR + tx] = p0;
            Ps[i_1 * PSTR + tx] = p1;
            float ls0 = p0, ls1 = p1;
#pragma unroll
            for (int d = 8; d; d >>= 1) {
                ls0 += __shfl_xor_sync(0xffffffffu, ls0, d);
                ls1 += __shfl_xor_sync(0xffffffffu, ls1, d);
            }
            l0 = l0 * al0 + ls0;
            l1 = l1 * al1 + ls1;
#pragma unroll
            for (int u = 0; u < 4; u++) { o0[u] *= al0; o1[u] *= al1; }

            __syncwarp();   // P rows 4w..4w+3 produced & consumed within warp w

            // ---- o += P @ V: output cols 4tx+u ----
#pragma unroll
            for (int jj4 = 0; jj4 < 4; jj4++) {
                float4 pa = *(const float4*)(Ps + i_0 * PSTR + 4 * jj4);
                float4 pb = *(const float4*)(Ps + i_1 * PSTR + 4 * jj4);
                const float* Vrow = Vc + (4 * jj4) * KSTR + 4 * tx;
                float4 v0 = *(const float4*)(Vrow);
                float4 v1 = *(const float4*)(Vrow + KSTR);
                float4 v2 = *(const float4*)(Vrow + 2 * KSTR);
                float4 v3 = *(const float4*)(Vrow + 3 * KSTR);
                o0[0] = fmaf(pa.x, v0.x, o0[0]); o0[1] = fmaf(pa.x, v0.y, o0[1]);
                o0[2] = fmaf(pa.x, v0.z, o0[2]); o0[3] = fmaf(pa.x, v0.w, o0[3]);
                o0[0] = fmaf(pa.y, v1.x, o0[0]); o0[1] = fmaf(pa.y, v1.y, o0[1]);
                o0[2] = fmaf(pa.y, v1.z, o0[2]); o0[3] = fmaf(pa.y, v1.w, o0[3]);
                o0[0] = fmaf(pa.z, v2.x, o0[0]); o0[1] = fmaf(pa.z, v2.y, o0[1]);
                o0[2] = fmaf(pa.z, v2.z, o0[2]); o0[3] = fmaf(pa.z, v2.w, o0[3]);
                o0[0] = fmaf(pa.w, v3.x, o0[0]); o0[1] = fmaf(pa.w, v3.y, o0[1]);
                o0[2] = fmaf(pa.w, v3.z, o0[2]); o0[3] = fmaf(pa.w, v3.w, o0[3]);
                o1[0] = fmaf(pb.x, v0.x, o1[0]); o1[1] = fmaf(pb.x, v0.y, o1[1]);
                o1[2] = fmaf(pb.x, v0.z, o1[2]); o1[3] = fmaf(pb.x, v0.w, o1[3]);
                o1[0] = fmaf(pb.y, v1.x, o1[0]); o1[1] = fmaf(pb.y, v1.y, o1[1]);
                o1[2] = fmaf(pb.y, v1.z, o1[2]); o1[3] = fmaf(pb.y, v1.w, o1[3]);
                o1[0] = fmaf(pb.z, v2.x, o1[0]); o1[1] = fmaf(pb.z, v2.y, o1[1]);
                o1[2] = fmaf(pb.z, v2.z, o1[2]); o1[3] = fmaf(pb.z, v2.w, o1[3]);
                o1[0] = fmaf(pb.w, v3.x, o1[0]); o1[1] = fmaf(pb.w, v3.y, o1[1]);
                o1[2] = fmaf(pb.w, v3.z, o1[2]); o1[3] = fmaf(pb.w, v3.w, o1[3]);
            }
            __syncthreads();   // buf fully consumed before overwrite
        }

        float f0 = mi0 / l0;   // l >= 1 always (masked rows contribute exp(0)=1)
        float f1 = mi1 / l1;
        float4 r0, r1;
        r0.x = o0[0] * f0; r0.y = o0[1] * f0; r0.z = o0[2] * f0; r0.w = o0[3] * f0;
        r1.x = o1[0] * f1; r1.y = o1[1] * f1; r1.z = o1[2] * f1; r1.w = o1[3] * f1;
        *(float4*)(out + (b * N + i0 + i_0) * DH + 4 * tx) = r0;
        *(float4*)(out + (b * N + i0 + i_1) * DH + 4 * tx) = r1;
        __syncthreads();
    }

    // ---- ticket-based copy of e (all blocks; attn blocks join after attn) ----
    for (;;) {
        if (t == 0) s_tk = atomicAdd(&g_ticket, 1);
        __syncthreads();
        int tk = s_tk;
        __syncthreads();
        if (tk >= NTICKETS) break;
        size_t base = (size_t)tk * CHUNK4 + t;
        float4 r[8];
#pragma unroll
        for (int k = 0; k < 8; k++) r[k] = e4[base + 256 * k];
#pragma unroll
        for (int k = 0; k < 8; k++) o4[base + 256 * k] = r[k];
        base += 2048;
#pragma unroll
        for (int k = 0; k < 8; k++) r[k] = e4[base + 256 * k];
#pragma unroll
        for (int k = 0; k < 8; k++) o4[base + 256 * k] = r[k];
    }
}

extern "C" void kernel_launch(void* const* d_in, const int* in_sizes, int n_in,
                              void* d_out, int out_size) {
    const float* x  = (const float*)d_in[0];
    const float* e  = (const float*)d_in[1];
    const int* mask = (const int*)d_in[2];
    const float* Wq = (const float*)d_in[3];
    const float* bq = (const float*)d_in[4];
    const float* Wk = (const float*)d_in[5];
    const float* bk = (const float*)d_in[6];
    const float* Wv = (const float*)d_in[7];
    const float* bv = (const float*)d_in[8];
    float* out = (float*)d_out;

    (void)in_sizes; (void)n_in; (void)out_size;

    const size_t OUT_ELEMS = (size_t)B * N * DH;   // 262144

    static void* ticket_addr = nullptr;
    if (!ticket_addr) {
        cudaGetSymbolAddress(&ticket_addr, g_ticket);
        cudaFuncSetAttribute(fused_kernel, cudaFuncAttributeMaxDynamicSharedMemorySize,
                             SMEM_FLOATS * (int)sizeof(float));
    }

    cudaMemsetAsync(ticket_addr, 0, sizeof(int));
    qkv_kernel<<<B * N, 256>>>(x, mask, Wq, bq, Wk, bk, Wv, bv);
    fused_kernel<<<GRID_BLOCKS, 256, SMEM_FLOATS * sizeof(float)>>>(
        mask, out, (const float4*)e, (float4*)(out + OUT_ELEMS));
}